// round 3
// baseline (speedup 1.0000x reference)
#include <cuda_runtime.h>

#define B 8
#define M 8192
#define N 8192
#define SPLITS 32
#define ROWS (M / SPLITS)            // 256 rows per split
#define TPB 128
#define COLS_PER_BLOCK (TPB * 4)     // 512 columns per block (4 floats per thread)
#define NBLK (N / COLS_PER_BLOCK)    // 16 column blocks

// Split-K partial sums: [SPLITS][B][N] floats = 8 MB device scratch.
__device__ float g_part[(size_t)SPLITS * B * N];

// Packed fp32x2 FMA: d = a*b + d  (sm_103a FFMA2, only reachable via PTX)
#define FMA_F32X2(d, a, b) \
    asm("fma.rn.f32x2 %0, %1, %2, %0;" : "+l"(d) : "l"(a), "l"(b))

__global__ void __launch_bounds__(TPB)
snn_gemv_split(const float* __restrict__ pre,   // [B][M]
               const float* __restrict__ W)     // [M][N] row-major
{
    // Pre-spikes staged pre-duplicated: pre_s2[m][b] = {p, p} so the packed
    // multiplier comes straight out of an LDS.128 broadcast. 16 KB smem.
    __shared__ unsigned long long pre_s2[ROWS][B];

    const int nb  = blockIdx.x;   // which 512-column tile
    const int s   = blockIdx.y;   // which M split
    const int tid = threadIdx.x;
    const int m0  = s * ROWS;

    for (int r = tid; r < ROWS; r += TPB) {
        #pragma unroll
        for (int b = 0; b < B; b++) {
            float p = pre[b * M + m0 + r];
            float2 pp = make_float2(p, p);
            pre_s2[r][b] = *reinterpret_cast<unsigned long long*>(&pp);
        }
    }
    __syncthreads();

    const int n0 = nb * COLS_PER_BLOCK + tid * 4;
    const ulonglong2* Wp =
        reinterpret_cast<const ulonglong2*>(W + (size_t)m0 * N + n0);
    // Row stride in ulonglong2 (16 B = 4 float) units: N/4 elements per row.
    const size_t ROW_STRIDE = N / 4;

    // acc[b][0] = packed cols {x,y}, acc[b][1] = packed cols {z,w}
    unsigned long long acc[B][2];
    #pragma unroll
    for (int b = 0; b < B; b++) { acc[b][0] = 0ull; acc[b][1] = 0ull; }

    #pragma unroll 4
    for (int m = 0; m < ROWS; m++) {
        ulonglong2 w = Wp[(size_t)m * ROW_STRIDE];   // LDG.128: 4 cols, 2 packed pairs

        unsigned long long p2[B];
        #pragma unroll
        for (int b = 0; b < B; b += 2) {
            ulonglong2 pp = *reinterpret_cast<const ulonglong2*>(&pre_s2[m][b]);
            p2[b]     = pp.x;                     // LDS.128 broadcast, 2 batches
            p2[b + 1] = pp.y;
        }

        #pragma unroll
        for (int b = 0; b < B; b++) {
            FMA_F32X2(acc[b][0], w.x, p2[b]);
            FMA_F32X2(acc[b][1], w.y, p2[b]);
        }
    }

    #pragma unroll
    for (int b = 0; b < B; b++) {
        float2 lo = *reinterpret_cast<float2*>(&acc[b][0]);
        float2 hi = *reinterpret_cast<float2*>(&acc[b][1]);
        float4 v = make_float4(lo.x, lo.y, hi.x, hi.y);
        *reinterpret_cast<float4*>(&g_part[((size_t)s * B + b) * N + n0]) = v;
    }
}

__global__ void __launch_bounds__(TPB)
snn_reduce(const float* __restrict__ thr,       // [B][N]
           const float* __restrict__ cst,       // [B][N]
           float* __restrict__ out)             // [B][N]
{
    const int idx  = blockIdx.x * blockDim.x + threadIdx.x;  // over B*N/2
    const int base = idx * 2;

    float2 sum = make_float2(0.f, 0.f);
    #pragma unroll 8
    for (int s = 0; s < SPLITS; s++) {
        float2 v = *reinterpret_cast<const float2*>(&g_part[(size_t)s * B * N + base]);
        sum.x += v.x; sum.y += v.y;
    }

    float2 t = *reinterpret_cast<const float2*>(&thr[base]);
    float2 c = *reinterpret_cast<const float2*>(&cst[base]);

    float2 o;
    o.x = fminf(fmaxf(sum.x + c.x - t.x, 0.f), 0.9f);
    o.y = fminf(fmaxf(sum.y + c.y - t.y, 0.f), 0.9f);

    *reinterpret_cast<float2*>(&out[base]) = o;
}

extern "C" void kernel_launch(void* const* d_in, const int* in_sizes, int n_in,
                              void* d_out, int out_size)
{
    const float* pre = (const float*)d_in[0];   // pre_spikes [8,1,8192]
    const float* W   = (const float*)d_in[1];   // W [8192,8192]
    const float* thr = (const float*)d_in[2];   // thr [8,1,8192]
    const float* cst = (const float*)d_in[3];   // const_inp [8,1,8192]
    float* out = (float*)d_out;                 // [8,1,8192]

    dim3 grid(NBLK, SPLITS);                    // 16 x 32 = 512 blocks
    snn_gemv_split<<<grid, TPB>>>(pre, W);

    const int total2 = (B * N) / 2;             // 32768 threads
    snn_reduce<<<total2 / TPB, TPB>>>(thr, cst, out);
}

// round 4
// speedup vs baseline: 1.6062x; 1.6062x over previous
#include <cuda_runtime.h>

#define B 8
#define M 8192
#define N 8192
#define SPLITS 64
#define ROWS (M / SPLITS)            // 128 rows per split
#define TPB 128
#define COLS_PER_BLOCK (TPB * 4)     // 512 columns per block (float4 per thread)
#define NBLK (N / COLS_PER_BLOCK)    // 16 column blocks -> grid 16x64 = 1024 blocks

// Split-K partial sums: [SPLITS][B][N] floats = 16 MB device scratch.
__device__ float g_part[(size_t)SPLITS * B * N];

__global__ void __launch_bounds__(TPB)
snn_gemv_split(const float* __restrict__ pre,   // [B][M]
               const float* __restrict__ W)     // [M][N] row-major
{
    __shared__ float pre_s[ROWS][B];

    const int nb  = blockIdx.x;
    const int s   = blockIdx.y;
    const int tid = threadIdx.x;
    const int m0  = s * ROWS;

    #pragma unroll
    for (int b = 0; b < B; b++)
        pre_s[tid][b] = pre[b * M + m0 + tid];
    __syncthreads();

    const int n0 = nb * COLS_PER_BLOCK + tid * 4;
    const float4* Wp = reinterpret_cast<const float4*>(W + (size_t)m0 * N + n0);
    const size_t S4 = N / 4;         // row stride in float4 units

    float4 acc[B];
    #pragma unroll
    for (int b = 0; b < B; b++)
        acc[b] = make_float4(0.f, 0.f, 0.f, 0.f);

    // Explicit 4-deep load batching: all 4 independent LDG.128s are issued
    // before any FMA consumes them -> MLP >= 4 per warp.
    #pragma unroll 1
    for (int m = 0; m < ROWS; m += 4) {
        float4 w0 = Wp[(size_t)(m + 0) * S4];
        float4 w1 = Wp[(size_t)(m + 1) * S4];
        float4 w2 = Wp[(size_t)(m + 2) * S4];
        float4 w3 = Wp[(size_t)(m + 3) * S4];

        #pragma unroll
        for (int j = 0; j < 4; j++) {
            float4 w = (j == 0) ? w0 : (j == 1) ? w1 : (j == 2) ? w2 : w3;
            float p[B];
            *reinterpret_cast<float4*>(&p[0]) =
                *reinterpret_cast<const float4*>(&pre_s[m + j][0]);
            *reinterpret_cast<float4*>(&p[4]) =
                *reinterpret_cast<const float4*>(&pre_s[m + j][4]);
            #pragma unroll
            for (int b = 0; b < B; b++) {
                acc[b].x += p[b] * w.x;
                acc[b].y += p[b] * w.y;
                acc[b].z += p[b] * w.z;
                acc[b].w += p[b] * w.w;
            }
        }
    }

    #pragma unroll
    for (int b = 0; b < B; b++)
        *reinterpret_cast<float4*>(&g_part[((size_t)s * B + b) * N + n0]) = acc[b];
}

__global__ void __launch_bounds__(256)
snn_reduce(const float* __restrict__ thr,       // [B][N]
           const float* __restrict__ cst,       // [B][N]
           float* __restrict__ out)             // [B][N]
{
    const int idx = blockIdx.x * 256 + threadIdx.x;   // over B*N (65536)

    float sum = 0.f;
    #pragma unroll
    for (int s = 0; s < SPLITS; s++)
        sum += g_part[(size_t)s * B * N + idx];       // 64 independent LDGs

    float o = sum + cst[idx] - thr[idx];
    out[idx] = fminf(fmaxf(o, 0.f), 0.9f);
}

extern "C" void kernel_launch(void* const* d_in, const int* in_sizes, int n_in,
                              void* d_out, int out_size)
{
    const float* pre = (const float*)d_in[0];   // pre_spikes [8,1,8192]
    const float* W   = (const float*)d_in[1];   // W [8192,8192]
    const float* thr = (const float*)d_in[2];   // thr [8,1,8192]
    const float* cst = (const float*)d_in[3];   // const_inp [8,1,8192]
    float* out = (float*)d_out;                 // [8,1,8192]

    dim3 grid(NBLK, SPLITS);                    // 16 x 64 = 1024 blocks
    snn_gemv_split<<<grid, TPB>>>(pre, W);

    snn_reduce<<<(B * N) / 256, 256>>>(thr, cst, out);
}

// round 6
// speedup vs baseline: 1.7379x; 1.0820x over previous
#include <cuda_runtime.h>

#define B 8
#define M 8192
#define N 8192
#define SPLITS 64
#define ROWS (M / SPLITS)            // 128 rows per split
#define TPB 128
#define COLS_PER_BLOCK (TPB * 4)     // 512 columns per block (4 floats per thread)
#define NBLK (N / COLS_PER_BLOCK)    // 16 -> grid 16x64 = 1024 blocks

// Split-K partial sums: [SPLITS][B][N] floats = 16 MB device scratch.
__device__ float g_part[(size_t)SPLITS * B * N];

// Packed fp32x2 FMA: d = a*b + d  (sm_103a FFMA2, only reachable via PTX)
#define FMA2(d, a, b) \
    asm("fma.rn.f32x2 %0, %1, %2, %0;" : "+l"(d) : "l"(a), "l"(b))

__global__ void __launch_bounds__(TPB, 7)
snn_gemv_split(const float* __restrict__ pre,   // [B][M]
               const float* __restrict__ W)     // [M][N] row-major
{
    // Pre-spikes pre-duplicated: pre_s2[r][b] = {p, p} (64-bit), so packed
    // multipliers come straight from LDS.128. 128*8*8 = 8 KB smem.
    __shared__ unsigned long long pre_s2[ROWS][B];

    const int nb  = blockIdx.x;
    const int s   = blockIdx.y;
    const int tid = threadIdx.x;
    const int m0  = s * ROWS;

    // tid == row (ROWS == TPB == 128)
    #pragma unroll
    for (int b = 0; b < B; b++) {
        float p = pre[b * M + m0 + tid];
        float2 pp = make_float2(p, p);
        pre_s2[tid][b] = *reinterpret_cast<unsigned long long*>(&pp);
    }
    __syncthreads();

    const int n0 = nb * COLS_PER_BLOCK + tid * 4;
    const ulonglong2* Wp =
        reinterpret_cast<const ulonglong2*>(W + (size_t)m0 * N + n0);
    const size_t S16 = N / 4;        // row stride in 16-byte (ulonglong2) units

    // acc[b][0] = packed cols {0,1}, acc[b][1] = packed cols {2,3}
    unsigned long long acc[B][2];
    #pragma unroll
    for (int b = 0; b < B; b++) { acc[b][0] = 0ull; acc[b][1] = 0ull; }

    // One row of packed-FMA work; W is an ulonglong2 (4 cols as 2 packed pairs)
    #define DO_ROW(WV, MI) do {                                              \
        const ulonglong2* ps =                                               \
            reinterpret_cast<const ulonglong2*>(&pre_s2[(MI)][0]);           \
        ulonglong2 pa = ps[0];  /* batches 0,1 */                            \
        ulonglong2 pb = ps[1];  /* batches 2,3 */                            \
        ulonglong2 pc = ps[2];  /* batches 4,5 */                            \
        ulonglong2 pd = ps[3];  /* batches 6,7 */                            \
        FMA2(acc[0][0], (WV).x, pa.x); FMA2(acc[0][1], (WV).y, pa.x);        \
        FMA2(acc[1][0], (WV).x, pa.y); FMA2(acc[1][1], (WV).y, pa.y);        \
        FMA2(acc[2][0], (WV).x, pb.x); FMA2(acc[2][1], (WV).y, pb.x);        \
        FMA2(acc[3][0], (WV).x, pb.y); FMA2(acc[3][1], (WV).y, pb.y);        \
        FMA2(acc[4][0], (WV).x, pc.x); FMA2(acc[4][1], (WV).y, pc.x);        \
        FMA2(acc[5][0], (WV).x, pc.y); FMA2(acc[5][1], (WV).y, pc.y);        \
        FMA2(acc[6][0], (WV).x, pd.x); FMA2(acc[6][1], (WV).y, pd.x);        \
        FMA2(acc[7][0], (WV).x, pd.y); FMA2(acc[7][1], (WV).y, pd.y);        \
    } while (0)

    // Explicit 4-deep load batching: 4 independent LDG.128s issued in program
    // order before any FMA consumes them -> MLP >= 4 per warp.
    #pragma unroll 1
    for (int m = 0; m < ROWS; m += 4) {
        ulonglong2 w0 = Wp[(size_t)(m + 0) * S16];
        ulonglong2 w1 = Wp[(size_t)(m + 1) * S16];
        ulonglong2 w2 = Wp[(size_t)(m + 2) * S16];
        ulonglong2 w3 = Wp[(size_t)(m + 3) * S16];
        DO_ROW(w0, m + 0);
        DO_ROW(w1, m + 1);
        DO_ROW(w2, m + 2);
        DO_ROW(w3, m + 3);
    }
    #undef DO_ROW

    #pragma unroll
    for (int b = 0; b < B; b++) {
        float2 lo = *reinterpret_cast<float2*>(&acc[b][0]);
        float2 hi = *reinterpret_cast<float2*>(&acc[b][1]);
        float4 v = make_float4(lo.x, lo.y, hi.x, hi.y);
        *reinterpret_cast<float4*>(&g_part[((size_t)s * B + b) * N + n0]) = v;
    }
}

__global__ void __launch_bounds__(256)
snn_reduce(const float* __restrict__ thr,       // [B][N]
           const float* __restrict__ cst,       // [B][N]
           float* __restrict__ out)             // [B][N]
{
    const int idx = blockIdx.x * 256 + threadIdx.x;   // over B*N (65536)

    float sum = 0.f;
    #pragma unroll
    for (int s = 0; s < SPLITS; s++)
        sum += g_part[(size_t)s * B * N + idx];       // 64 independent LDGs

    float o = sum + cst[idx] - thr[idx];
    out[idx] = fminf(fmaxf(o, 0.f), 0.9f);
}

extern "C" void kernel_launch(void* const* d_in, const int* in_sizes, int n_in,
                              void* d_out, int out_size)
{
    const float* pre = (const float*)d_in[0];   // pre_spikes [8,1,8192]
    const float* W   = (const float*)d_in[1];   // W [8192,8192]
    const float* thr = (const float*)d_in[2];   // thr [8,1,8192]
    const float* cst = (const float*)d_in[3];   // const_inp [8,1,8192]
    float* out = (float*)d_out;                 // [8,1,8192]

    dim3 grid(NBLK, SPLITS);                    // 16 x 64 = 1024 blocks
    snn_gemv_split<<<grid, TPB>>>(pre, W);

    snn_reduce<<<(B * N) / 256, 256>>>(thr, cst, out);
}